// round 1
// baseline (speedup 1.0000x reference)
#include <cuda_runtime.h>

typedef unsigned long long ull;

#define B_TOK 32768
#define H_DIM 4096
#define G_NUM 16
#define EPG_N 16
#define E_NUM 256

#define TOK  128    // tokens per CTA tile
#define KC   64     // K chunk
#define ASTR 68     // KC + 4 pad (bank-conflict mitigation)
#define NTHR 256

// scratch (no allocations allowed)
__device__ int g_cnt[G_NUM];
__device__ int g_bucket[G_NUM * B_TOK];

__device__ __forceinline__ void ffma2(ull& acc, ull a, ull w) {
    // packed f32x2 FMA (FFMA2) — 2 fp32 MACs per instruction
    asm volatile("fma.rn.f32x2 %0, %1, %2, %0;" : "+l"(acc) : "l"(a), "l"(w));
}

__device__ __forceinline__ float fsum2(ull v) {
    union { ull u; float2 f; } t; t.u = v;
    return t.f.x + t.f.y;
}

__global__ void zero_cnt_kernel() {
    if (threadIdx.x < G_NUM) g_cnt[threadIdx.x] = 0;
}

// ---------------------------------------------------------------------------
// Phase 1: group logits GEMV [TOK x 16], argmax, bucket tokens by group.
// Thread blocking: 4 tokens x 2 outputs per thread (256 threads, 128x16 tile).
// ---------------------------------------------------------------------------
__global__ void __launch_bounds__(NTHR, 2) group_route_kernel(
    const float* __restrict__ hs, const float* __restrict__ gw)
{
    __shared__ float sA[TOK][ASTR];
    __shared__ float sW[G_NUM][ASTR];
    __shared__ int scnt[G_NUM];
    __shared__ int sbase[G_NUM];

    const int tid = threadIdx.x;
    const int b0  = blockIdx.x * TOK;
    const int tx  = tid & 7;          // output pair {2tx, 2tx+1}
    const int ty  = tid >> 3;         // token quad base 4*ty
    const int c4  = (tid & 15) * 4;   // loader column (floats)
    const int rg  = tid >> 4;         // loader row group

    ull acc[4][2];
#pragma unroll
    for (int t = 0; t < 4; t++) { acc[t][0] = 0ULL; acc[t][1] = 0ULL; }

    for (int k0 = 0; k0 < H_DIM; k0 += KC) {
        __syncthreads();
#pragma unroll
        for (int i = 0; i < 8; i++) {
            int row = rg + i * 16;
            *(float4*)&sA[row][c4] =
                *(const float4*)&hs[(size_t)(b0 + row) * H_DIM + k0 + c4];
        }
        *(float4*)&sW[rg][c4] = *(const float4*)&gw[(size_t)rg * H_DIM + k0 + c4];
        __syncthreads();

#pragma unroll
        for (int kk = 0; kk < KC; kk += 4) {
            ulonglong2 w0 = *(const ulonglong2*)&sW[2 * tx + 0][kk];
            ulonglong2 w1 = *(const ulonglong2*)&sW[2 * tx + 1][kk];
#pragma unroll
            for (int t = 0; t < 4; t++) {
                ulonglong2 a = *(const ulonglong2*)&sA[4 * ty + t][kk];
                ffma2(acc[t][0], a.x, w0.x);
                ffma2(acc[t][0], a.y, w0.y);
                ffma2(acc[t][1], a.x, w1.x);
                ffma2(acc[t][1], a.y, w1.y);
            }
        }
    }

    __syncthreads();
    float (*sC)[17] = reinterpret_cast<float(*)[17]>(&sA[0][0]);
#pragma unroll
    for (int t = 0; t < 4; t++) {
        sC[4 * ty + t][2 * tx + 0] = fsum2(acc[t][0]);
        sC[4 * ty + t][2 * tx + 1] = fsum2(acc[t][1]);
    }
    if (tid < G_NUM) scnt[tid] = 0;
    __syncthreads();

    int bg = 0, loff = 0;
    if (tid < TOK) {
        float best = sC[tid][0];
#pragma unroll
        for (int g = 1; g < G_NUM; g++) {
            float v = sC[tid][g];
            if (v > best) { best = v; bg = g; }   // first-index-wins like jnp.argmax
        }
        loff = atomicAdd(&scnt[bg], 1);
    }
    __syncthreads();
    if (tid < G_NUM) sbase[tid] = atomicAdd(&g_cnt[tid], scnt[tid]);
    __syncthreads();
    if (tid < TOK) g_bucket[bg * B_TOK + sbase[bg] + loff] = b0 + tid;
}

// ---------------------------------------------------------------------------
// Phase 2: per-group expert GEMM over bucketed tokens + softmax/argmax epilogue
// + full [B,E] output row write (zeros outside selected block).
// ---------------------------------------------------------------------------
__global__ void __launch_bounds__(NTHR, 2) expert_route_kernel(
    const float* __restrict__ hs, const float* __restrict__ ew,
    float* __restrict__ out)
{
    __shared__ float sA[TOK][ASTR];
    __shared__ float sW[EPG_N][ASTR];
    __shared__ int stok[TOK];

    const int tid = threadIdx.x;
    const int g   = blockIdx.x;
    const int cnt = g_cnt[g];
    const float* wg = ew + (size_t)g * EPG_N * H_DIM;

    const int tx = tid & 7;
    const int ty = tid >> 3;
    const int c4 = (tid & 15) * 4;
    const int rg = tid >> 4;

    const size_t OUT_SEL = (size_t)B_TOK * E_NUM;
    const size_t OUT_WGT = OUT_SEL + B_TOK;

    for (int tile = blockIdx.y; tile * TOK < cnt; tile += gridDim.y) {
        __syncthreads();
        if (tid < TOK) {
            int idx = tile * TOK + tid;
            stok[tid] = (idx < cnt) ? g_bucket[g * B_TOK + idx] : -1;
        }
        __syncthreads();

        ull acc[4][2];
#pragma unroll
        for (int t = 0; t < 4; t++) { acc[t][0] = 0ULL; acc[t][1] = 0ULL; }

        for (int k0 = 0; k0 < H_DIM; k0 += KC) {
            if (k0) __syncthreads();
#pragma unroll
            for (int i = 0; i < 8; i++) {
                int row = rg + i * 16;
                int tok = stok[row];
                if (tok >= 0)
                    *(float4*)&sA[row][c4] =
                        *(const float4*)&hs[(size_t)tok * H_DIM + k0 + c4];
            }
            *(float4*)&sW[rg][c4] = *(const float4*)&wg[(size_t)rg * H_DIM + k0 + c4];
            __syncthreads();

#pragma unroll
            for (int kk = 0; kk < KC; kk += 4) {
                ulonglong2 w0 = *(const ulonglong2*)&sW[2 * tx + 0][kk];
                ulonglong2 w1 = *(const ulonglong2*)&sW[2 * tx + 1][kk];
#pragma unroll
                for (int t = 0; t < 4; t++) {
                    ulonglong2 a = *(const ulonglong2*)&sA[4 * ty + t][kk];
                    ffma2(acc[t][0], a.x, w0.x);
                    ffma2(acc[t][0], a.y, w0.y);
                    ffma2(acc[t][1], a.x, w1.x);
                    ffma2(acc[t][1], a.y, w1.y);
                }
            }
        }

        __syncthreads();
        float (*sC)[17] = reinterpret_cast<float(*)[17]>(&sA[0][0]);
#pragma unroll
        for (int t = 0; t < 4; t++) {
            sC[4 * ty + t][2 * tx + 0] = fsum2(acc[t][0]);
            sC[4 * ty + t][2 * tx + 1] = fsum2(acc[t][1]);
        }
        __syncthreads();

        // per-token epilogue: softmax over 16 experts, argmax, weight
        if (tid < TOK && stok[tid] >= 0) {
            int token = stok[tid];
            float m = sC[tid][0];
            int bi = 0;
#pragma unroll
            for (int e = 1; e < EPG_N; e++) {
                float v = sC[tid][e];
                if (v > m) { m = v; bi = e; }
            }
            float s = 0.0f;
#pragma unroll
            for (int e = 0; e < EPG_N; e++) s += expf(sC[tid][e] - m);
            out[OUT_SEL + token] = (float)(g * EPG_N + bi);
            out[OUT_WGT + token] = 1.0f / s;   // exp(max-max)/sum
        }

        // cooperative all_expert_logits row write: 64 threads per token row,
        // 4 token rows per iteration, coalesced 1KB stores per row.
        const int slot_off = tid >> 6;   // 0..3
        const int cc4 = tid & 63;        // float4 column index in [0,64)
        for (int tb = 0; tb < TOK; tb += 4) {
            int slot = tb + slot_off;
            int token = stok[slot];
            if (token >= 0) {
                float4 v = make_float4(0.f, 0.f, 0.f, 0.f);
                if ((cc4 >> 2) == g) {
                    int lo = (cc4 & 3) * 4;
                    v = make_float4(sC[slot][lo], sC[slot][lo + 1],
                                    sC[slot][lo + 2], sC[slot][lo + 3]);
                }
                *(float4*)&out[(size_t)token * E_NUM + cc4 * 4] = v;
            }
        }
    }
}

extern "C" void kernel_launch(void* const* d_in, const int* in_sizes, int n_in,
                              void* d_out, int out_size) {
    const float* hs = (const float*)d_in[0];   // [32768, 4096]
    const float* gw = (const float*)d_in[1];   // [16, 4096]
    const float* ew = (const float*)d_in[2];   // [16, 16, 4096]
    float* out = (float*)d_out;                // [B*E] logits | [B] sel | [B] wgt

    zero_cnt_kernel<<<1, 32>>>();
    group_route_kernel<<<B_TOK / TOK, NTHR>>>(hs, gw);
    dim3 grid2(G_NUM, 24);
    expert_route_kernel<<<grid2, NTHR>>>(hs, ew, out);
}